// round 11
// baseline (speedup 1.0000x reference)
#include <cuda_runtime.h>
#include <stdint.h>

#define BATCH 128
#define N_RX 34
#define IMG_H 512
#define IMG_W 512
#define N_PIX (IMG_H * IMG_W)

#define TPB 256
#define TILE_PX 1024                    // pixels per tile = TPB * 4
#define TILES_PER_GROUP 4               // 4 tiles * 4KB = 16KB per block
#define SPAN_PX (TILES_PER_GROUP * TILE_PX)   // 4096 pixels
#define GROUPS 64                       // 64 * 4096 = 262144 = N_PIX

// ---------------------------------------------------------------------------
// Zero-first, fixup-after (R10 structure), occupancy-repaired:
//   - __launch_bounds__(256, 8) keeps regs <= 32 -> 8 blocks/SM resident.
//   - only the scattered x_vecs float4 is prefetched before streaming;
//     all weight loads happen in the epilogue (L2-hot, latency absorbed).
// ---------------------------------------------------------------------------
__global__ void __launch_bounds__(TPB, 8)
vec2im_kernel(const float* __restrict__ x_vecs,
              const float* __restrict__ dw,
              const float* __restrict__ db,
              const float* __restrict__ cw,
              const float* __restrict__ cb,
              float* __restrict__ out) {
    __shared__ int s_off[N_RX];

    const int group = blockIdx.x;       // 0..63
    const int ch    = blockIdx.y;       // 0..1
    const int b     = blockIdx.z;       // 0..127
    const int tid   = threadIdx.x;

    // ---- (1) issue the scattered point load early (consumed after stream) ----
    float4 v;
    if (tid < N_RX) {
        v = *reinterpret_cast<const float4*>(
                x_vecs + ((size_t)b * N_RX + tid) * 4);
    }

    // ---- (2) pure streaming: 4 x STG.128 of zeros, nothing in front ----
    const int px_group0 = group * SPAN_PX;
    float4* o4 = reinterpret_cast<float4*>(
                     out + (size_t)(b * 2 + ch) * N_PIX + px_group0) + tid;
    const float4 z = make_float4(0.f, 0.f, 0.f, 0.f);
    #pragma unroll
    for (int t = 0; t < TILES_PER_GROUP; t++) {
        o4[t * (TILE_PX / 4)] = z;
    }

    // ---- (3) publish offsets; bar orders fixup after zeros (same-addr, CTA) ----
    int off = -1;
    if (tid < N_RX) {
        int xx = (int)rintf(v.y);       // col 1 -> x
        int yy = (int)rintf(v.z);       // col 2 -> y
        off = yy * IMG_W + xx;
        s_off[tid] = off;
    }
    __syncthreads();

    // ---- (4) fixup: only the block owning this point's span writes ----
    if (tid < N_RX) {
        int d = off - px_group0;
        if ((unsigned)d < (unsigned)SPAN_PX) {
            // Last-wins: suppress if any LATER rx hits the same pixel.
            bool write = true;
            #pragma unroll
            for (int rr = 0; rr < N_RX; rr++) {
                if (rr > tid && s_off[rr] == off) write = false;
            }
            if (write) {
                float raw = v.x;
                float val;
                if (ch) {
                    val = raw;
                } else {
                    float mask = (raw != 0.0f) ? 1.0f : 0.0f;
                    float p = raw * dw[tid] + mask * db[tid];
                    int cat = (int)v.w;
                    val = p * cw[cat] + mask * cb[cat];
                }
                out[(size_t)(b * 2 + ch) * N_PIX + off] = val;
            }
        }
    }
}

// ---------------------------------------------------------------------------
extern "C" void kernel_launch(void* const* d_in, const int* in_sizes, int n_in,
                              void* d_out, int out_size) {
    const float* x_vecs = (const float*)d_in[0];
    const float* dw     = (const float*)d_in[1];
    const float* db     = (const float*)d_in[2];
    const float* cw     = (const float*)d_in[3];
    const float* cb     = (const float*)d_in[4];
    float* out = (float*)d_out;

    dim3 grid(GROUPS, 2, BATCH);        // 16384 blocks, 16KB each
    vec2im_kernel<<<grid, TPB>>>(x_vecs, dw, db, cw, cb, out);
}

// round 12
// speedup vs baseline: 1.0063x; 1.0063x over previous
#include <cuda_runtime.h>
#include <stdint.h>

#define BATCH 128
#define N_RX 34
#define IMG_H 512
#define IMG_W 512
#define N_PIX (IMG_H * IMG_W)

#define TPB 256
#define TILES_PER_GROUP 4               // 16KB per block (unchanged from R10)
#define SPAN_PX (TILES_PER_GROUP * TPB * 4)   // 4096 pixels
#define GROUPS 64                       // 64 * 4096 = 262144 = N_PIX

// ---------------------------------------------------------------------------
// R10 structure (zero-first, fixup-after), with the streaming loop upgraded
// to Blackwell 256-bit stores: 2 x STG.256 per thread instead of 4 x STG.128.
//   1) threads 0..33 issue their point LDG (consumed only after streaming)
//   2) all threads stream 2 unconditional 32B zero stores
//   3) __syncthreads() orders fixup stores after zeros (same-address, CTA)
//   4) threads 0..33 fix up owned points; smem suppress-scan = exact
//      last-wins dedup.
// ---------------------------------------------------------------------------
__global__ void __launch_bounds__(TPB)
vec2im_kernel(const float* __restrict__ x_vecs,
              const float* __restrict__ dw,
              const float* __restrict__ db,
              const float* __restrict__ cw,
              const float* __restrict__ cb,
              float* __restrict__ out) {
    __shared__ int s_off[N_RX];

    const int group = blockIdx.x;       // 0..63
    const int ch    = blockIdx.y;       // 0..1
    const int b     = blockIdx.z;       // 0..127
    const int tid   = threadIdx.x;

    // ---- (1) issue the scattered point load early ----
    float4 v;
    float w_dw = 0.f, w_db = 0.f;
    if (tid < N_RX) {
        v    = *reinterpret_cast<const float4*>(
                   x_vecs + ((size_t)b * N_RX + tid) * 4);
        w_dw = dw[tid];
        w_db = db[tid];
    }

    // ---- (2) pure streaming: 2 x 32B zero stores per thread ----
    const int px_group0 = group * SPAN_PX;
    float* obase = out + (size_t)(b * 2 + ch) * N_PIX + px_group0;
    // 32B units: thread covers bytes [tid*32, tid*32+32) then + TPB*32
    float* st0 = obase + tid * 8;
    float* st1 = obase + (TPB + tid) * 8;
    const float zf = 0.0f;
    asm volatile(
        "st.global.v8.f32 [%0], {%2,%2,%2,%2,%2,%2,%2,%2};\n\t"
        "st.global.v8.f32 [%1], {%2,%2,%2,%2,%2,%2,%2,%2};\n\t"
        :: "l"(st0), "l"(st1), "f"(zf) : "memory");

    // ---- (3) publish offsets; bar orders fixup after zeros ----
    int off = -1;
    if (tid < N_RX) {
        int xx = (int)rintf(v.y);       // col 1 -> x
        int yy = (int)rintf(v.z);       // col 2 -> y
        off = yy * IMG_W + xx;
        s_off[tid] = off;
    }
    __syncthreads();

    // ---- (4) fixup: only the block owning this point's span writes ----
    if (tid < N_RX) {
        int d = off - px_group0;
        if ((unsigned)d < (unsigned)SPAN_PX) {
            bool write = true;
            #pragma unroll
            for (int rr = 0; rr < N_RX; rr++) {
                if (rr > tid && s_off[rr] == off) write = false;
            }
            if (write) {
                float raw = v.x;
                float val;
                if (ch) {
                    val = raw;
                } else {
                    float mask = (raw != 0.0f) ? 1.0f : 0.0f;
                    float p = raw * w_dw + mask * w_db;
                    int cat = (int)v.w;
                    val = p * cw[cat] + mask * cb[cat];
                }
                out[(size_t)(b * 2 + ch) * N_PIX + off] = val;
            }
        }
    }
}

// ---------------------------------------------------------------------------
extern "C" void kernel_launch(void* const* d_in, const int* in_sizes, int n_in,
                              void* d_out, int out_size) {
    const float* x_vecs = (const float*)d_in[0];
    const float* dw     = (const float*)d_in[1];
    const float* db     = (const float*)d_in[2];
    const float* cw     = (const float*)d_in[3];
    const float* cb     = (const float*)d_in[4];
    float* out = (float*)d_out;

    dim3 grid(GROUPS, 2, BATCH);        // 16384 blocks, 16KB each
    vec2im_kernel<<<grid, TPB>>>(x_vecs, dw, db, cw, cb, out);
}

// round 14
// speedup vs baseline: 1.0333x; 1.0268x over previous
#include <cuda_runtime.h>
#include <stdint.h>

#define BATCH 128
#define N_RX 34
#define IMG_H 512
#define IMG_W 512
#define N_PIX (IMG_H * IMG_W)

#define TPB 256
#define TILE_PX 1024                    // pixels per tile = TPB * 4
#define TILES_PER_GROUP 4               // 4 tiles * 4KB = 16KB per block
#define SPAN_PX (TILES_PER_GROUP * TILE_PX)   // 4096 pixels
#define GROUPS 64                       // 64 * 4096 = 262144 = N_PIX

// ---------------------------------------------------------------------------
// R10 structure (the measured best: 36.5us kernel @ 7.35 TB/s stores), with
// the zero stream issued as evict-first (st.global.cs) so the write-once
// sectors drain from L2 aggressively and the hot fixup/read set stays
// resident.
//   1) threads 0..33 issue their point + weight LDGs (consumed after stream)
//   2) all threads stream 4 unconditional STG.128.cs zeros
//   3) __syncthreads() orders fixup stores after zeros (same-address, CTA)
//   4) threads 0..33 fix up owned points; smem suppress-scan = exact
//      last-wins dedup.
// ---------------------------------------------------------------------------
__global__ void __launch_bounds__(TPB)
vec2im_kernel(const float* __restrict__ x_vecs,
              const float* __restrict__ dw,
              const float* __restrict__ db,
              const float* __restrict__ cw,
              const float* __restrict__ cb,
              float* __restrict__ out) {
    __shared__ int s_off[N_RX];

    const int group = blockIdx.x;       // 0..63
    const int ch    = blockIdx.y;       // 0..1
    const int b     = blockIdx.z;       // 0..127
    const int tid   = threadIdx.x;

    // ---- (1) issue the scattered point + weight loads early ----
    float4 v;
    float w_dw = 0.f, w_db = 0.f;
    if (tid < N_RX) {
        v    = *reinterpret_cast<const float4*>(
                   x_vecs + ((size_t)b * N_RX + tid) * 4);
        w_dw = dw[tid];
        w_db = db[tid];
    }

    // ---- (2) pure streaming: 4 x STG.128 evict-first zeros ----
    const int px_group0 = group * SPAN_PX;
    float4* o4 = reinterpret_cast<float4*>(
                     out + (size_t)(b * 2 + ch) * N_PIX + px_group0) + tid;
    const float4 z = make_float4(0.f, 0.f, 0.f, 0.f);
    #pragma unroll
    for (int t = 0; t < TILES_PER_GROUP; t++) {
        __stcs(o4 + t * (TILE_PX / 4), z);
    }

    // ---- (3) publish offsets; bar orders fixup after zeros ----
    int off = -1;
    if (tid < N_RX) {
        int xx = (int)rintf(v.y);       // col 1 -> x
        int yy = (int)rintf(v.z);       // col 2 -> y
        off = yy * IMG_W + xx;
        s_off[tid] = off;
    }
    __syncthreads();

    // ---- (4) fixup: only the block owning this point's span writes ----
    if (tid < N_RX) {
        int d = off - px_group0;
        if ((unsigned)d < (unsigned)SPAN_PX) {
            // Last-wins: suppress if any LATER rx hits the same pixel.
            bool write = true;
            #pragma unroll
            for (int rr = 0; rr < N_RX; rr++) {
                if (rr > tid && s_off[rr] == off) write = false;
            }
            if (write) {
                float raw = v.x;
                float val;
                if (ch) {
                    val = raw;
                } else {
                    float mask = (raw != 0.0f) ? 1.0f : 0.0f;
                    float p = raw * w_dw + mask * w_db;
                    int cat = (int)v.w;
                    val = p * cw[cat] + mask * cb[cat];
                }
                out[(size_t)(b * 2 + ch) * N_PIX + off] = val;
            }
        }
    }
}

// ---------------------------------------------------------------------------
extern "C" void kernel_launch(void* const* d_in, const int* in_sizes, int n_in,
                              void* d_out, int out_size) {
    const float* x_vecs = (const float*)d_in[0];
    const float* dw     = (const float*)d_in[1];
    const float* db     = (const float*)d_in[2];
    const float* cw     = (const float*)d_in[3];
    const float* cb     = (const float*)d_in[4];
    float* out = (float*)d_out;

    dim3 grid(GROUPS, 2, BATCH);        // 16384 blocks, 16KB each
    vec2im_kernel<<<grid, TPB>>>(x_vecs, dw, db, cw, cb, out);
}

// round 15
// speedup vs baseline: 1.0435x; 1.0098x over previous
#include <cuda_runtime.h>
#include <stdint.h>

#define BATCH 128
#define N_RX 34
#define IMG_H 512
#define IMG_W 512
#define N_PIX (IMG_H * IMG_W)

#define TPB 256
#define TILE_PX 1024                    // pixels per tile = TPB * 4
#define TILES_PER_GROUP 2               // 2 tiles * 4KB = 8KB per block
#define SPAN_PX (TILES_PER_GROUP * TILE_PX)   // 2048 pixels
#define GROUPS 128                      // 128 * 2048 = 262144 = N_PIX

// ---------------------------------------------------------------------------
// Zero-first, fixup-after (R10/R14 structure, measured 36.5us @ 7.35TB/s),
// span halved to 8KB: 32768 blocks -> 27.7 waves -> minimal wave-quantization
// and cross-CTA spread (the only residual loss the sweep hasn't eliminated).
//   1) threads 0..33 issue their point + weight LDGs (consumed after stream)
//   2) all threads stream 2 unconditional STG.128.cs zeros (nothing in front)
//   3) __syncthreads() orders fixup stores after zeros (same-address, CTA)
//   4) threads 0..33 fix up owned points; smem suppress-scan = exact
//      last-wins dedup.
// ---------------------------------------------------------------------------
__global__ void __launch_bounds__(TPB)
vec2im_kernel(const float* __restrict__ x_vecs,
              const float* __restrict__ dw,
              const float* __restrict__ db,
              const float* __restrict__ cw,
              const float* __restrict__ cb,
              float* __restrict__ out) {
    __shared__ int s_off[N_RX];

    const int group = blockIdx.x;       // 0..127
    const int ch    = blockIdx.y;       // 0..1
    const int b     = blockIdx.z;       // 0..127
    const int tid   = threadIdx.x;

    // ---- (1) issue the scattered point + weight loads early ----
    float4 v;
    float w_dw = 0.f, w_db = 0.f;
    if (tid < N_RX) {
        v    = *reinterpret_cast<const float4*>(
                   x_vecs + ((size_t)b * N_RX + tid) * 4);
        w_dw = dw[tid];
        w_db = db[tid];
    }

    // ---- (2) pure streaming: 2 x STG.128 evict-first zeros ----
    const int px_group0 = group * SPAN_PX;
    float4* o4 = reinterpret_cast<float4*>(
                     out + (size_t)(b * 2 + ch) * N_PIX + px_group0) + tid;
    const float4 z = make_float4(0.f, 0.f, 0.f, 0.f);
    #pragma unroll
    for (int t = 0; t < TILES_PER_GROUP; t++) {
        __stcs(o4 + t * (TILE_PX / 4), z);
    }

    // ---- (3) publish offsets; bar orders fixup after zeros ----
    int off = -1;
    if (tid < N_RX) {
        int xx = (int)rintf(v.y);       // col 1 -> x
        int yy = (int)rintf(v.z);       // col 2 -> y
        off = yy * IMG_W + xx;
        s_off[tid] = off;
    }
    __syncthreads();

    // ---- (4) fixup: only the block owning this point's span writes ----
    if (tid < N_RX) {
        int d = off - px_group0;
        if ((unsigned)d < (unsigned)SPAN_PX) {
            // Last-wins: suppress if any LATER rx hits the same pixel.
            bool write = true;
            #pragma unroll
            for (int rr = 0; rr < N_RX; rr++) {
                if (rr > tid && s_off[rr] == off) write = false;
            }
            if (write) {
                float raw = v.x;
                float val;
                if (ch) {
                    val = raw;
                } else {
                    float mask = (raw != 0.0f) ? 1.0f : 0.0f;
                    float p = raw * w_dw + mask * w_db;
                    int cat = (int)v.w;
                    val = p * cw[cat] + mask * cb[cat];
                }
                out[(size_t)(b * 2 + ch) * N_PIX + off] = val;
            }
        }
    }
}

// ---------------------------------------------------------------------------
extern "C" void kernel_launch(void* const* d_in, const int* in_sizes, int n_in,
                              void* d_out, int out_size) {
    const float* x_vecs = (const float*)d_in[0];
    const float* dw     = (const float*)d_in[1];
    const float* db     = (const float*)d_in[2];
    const float* cw     = (const float*)d_in[3];
    const float* cb     = (const float*)d_in[4];
    float* out = (float*)d_out;

    dim3 grid(GROUPS, 2, BATCH);        // 32768 blocks, 8KB each
    vec2im_kernel<<<grid, TPB>>>(x_vecs, dw, db, cw, cb, out);
}